// round 9
// baseline (speedup 1.0000x reference)
#include <cuda_runtime.h>
#include <cstdint>

// Masked per-graph mean pooling — TMA bulk-copy pipeline version.
// Inputs (metadata order):
//   d_in[0]: node_embeddings float32 [B*N, D] = [4096*64, 256]
//   d_in[1]: op_idx          int32   [B, N]   = [4096, 64]
// Output: float32 [B, D] = [4096, 256]
//
// out[b, :] = sum_{n: op[b,n]!=5} h[b,n,:] / max(count, 1)
//
// One CTA per graph, 256 threads. The 64 KB embedding tile is streamed via
// cp.async.bulk in 8 KB chunks (8 rows) through a 3-stage smem ring with
// mbarrier full/empty handshakes. HBM sees long contiguous bursts instead of
// ~2300 interleaved 128B LDG streams -> better row-buffer locality.

#define SKIP_OP     5
#define NNODES      64
#define DIM         256
#define DIM4        (DIM / 4)          // 64 float4 per row
#define CHUNK_ROWS  8
#define NCHUNKS     (NNODES / CHUNK_ROWS)   // 8
#define STAGES      3
#define CHUNK_BYTES (CHUNK_ROWS * DIM * 4)  // 8192

__device__ __forceinline__ uint32_t s2u(const void* p) {
    uint32_t a;
    asm("{ .reg .u64 t; cvta.to.shared.u64 t, %1; cvt.u32.u64 %0, t; }"
        : "=r"(a) : "l"(p));
    return a;
}
__device__ __forceinline__ void mbar_init(uint32_t m, uint32_t cnt) {
    asm volatile("mbarrier.init.shared.b64 [%0], %1;" :: "r"(m), "r"(cnt) : "memory");
}
__device__ __forceinline__ void mbar_expect_tx(uint32_t m, uint32_t tx) {
    asm volatile("mbarrier.arrive.expect_tx.shared.b64 _, [%0], %1;"
                 :: "r"(m), "r"(tx) : "memory");
}
__device__ __forceinline__ void mbar_arrive(uint32_t m) {
    asm volatile("mbarrier.arrive.shared.b64 _, [%0];" :: "r"(m) : "memory");
}
__device__ __forceinline__ void mbar_wait(uint32_t m, uint32_t parity) {
    asm volatile(
        "{\n\t.reg .pred P;\n\t"
        "WL_%=:\n\t"
        "mbarrier.try_wait.parity.shared.b64 P, [%0], %1;\n\t"
        "@P bra WD_%=;\n\t"
        "bra WL_%=;\n\t"
        "WD_%=:\n\t}"
        :: "r"(m), "r"(parity) : "memory");
}
__device__ __forceinline__ void tma_bulk(uint32_t dst, const void* src,
                                         uint32_t bytes, uint32_t mbar) {
    asm volatile(
        "cp.async.bulk.shared::cluster.global.mbarrier::complete_tx::bytes "
        "[%0], [%1], %2, [%3];"
        :: "r"(dst), "l"(src), "r"(bytes), "r"(mbar) : "memory");
}

__global__ __launch_bounds__(256, 8)
void readout_kernel(const float* __restrict__ h,
                    const int* __restrict__ op,
                    float* __restrict__ out)
{
    __shared__ __align__(128) float4  buf[STAGES][CHUNK_ROWS * DIM4]; // 24 KB
    __shared__ __align__(8)  uint64_t mb_full[STAGES];
    __shared__ __align__(8)  uint64_t mb_empty[STAGES];
    __shared__ float  mask[NNODES];
    __shared__ int    wcnt[2];
    __shared__ float4 partial[4][DIM4];                               // 4 KB

    const int b   = blockIdx.x;
    const int tid = threadIdx.x;
    const float* hb = h + (size_t)b * NNODES * DIM;

    // Mask + count (ballot over warps 0,1).
    if (tid < NNODES) {
        const bool keep = (op[(size_t)b * NNODES + tid] != SKIP_OP);
        mask[tid] = keep ? 1.0f : 0.0f;
        const unsigned bal = __ballot_sync(0xffffffffu, keep);
        if ((tid & 31) == 0) wcnt[tid >> 5] = __popc(bal);
    }
    if (tid == 0) {
        for (int s = 0; s < STAGES; s++) {
            mbar_init(s2u(&mb_full[s]),  1);     // expect_tx is the single arrival
            mbar_init(s2u(&mb_empty[s]), 256);   // every consumer thread arrives
        }
    }
    asm volatile("fence.proxy.async.shared::cta;" ::: "memory");
    __syncthreads();

    // Prologue: fill the ring.
    if (tid == 0) {
#pragma unroll
        for (int c = 0; c < STAGES; c++) {
            const uint32_t f = s2u(&mb_full[c]);
            mbar_expect_tx(f, CHUNK_BYTES);
            tma_bulk(s2u(&buf[c][0]), hb + c * CHUNK_ROWS * DIM, CHUNK_BYTES, f);
        }
    }

    const int col = tid & (DIM4 - 1);   // float4 column 0..63
    const int g   = tid >> 6;           // row group 0..3 (rows g, g+4 per chunk)

    float4 acc = make_float4(0.f, 0.f, 0.f, 0.f);

    for (int c = 0; c < NCHUNKS; c++) {
        const int s  = c % STAGES;
        const int ph = (c / STAGES) & 1;
        mbar_wait(s2u(&mb_full[s]), ph);

#pragma unroll
        for (int rr = g; rr < CHUNK_ROWS; rr += 4) {
            const float  m = mask[c * CHUNK_ROWS + rr];
            const float4 v = buf[s][rr * DIM4 + col];
            acc.x = fmaf(m, v.x, acc.x);
            acc.y = fmaf(m, v.y, acc.y);
            acc.z = fmaf(m, v.z, acc.z);
            acc.w = fmaf(m, v.w, acc.w);
        }
        mbar_arrive(s2u(&mb_empty[s]));

        // Refill this stage with chunk c+STAGES once all consumers released it.
        const int cn = c + STAGES;
        if (tid == 0 && cn < NCHUNKS) {
            mbar_wait(s2u(&mb_empty[s]), (c / STAGES) & 1);
            const uint32_t f = s2u(&mb_full[s]);
            mbar_expect_tx(f, CHUNK_BYTES);
            tma_bulk(s2u(&buf[s][0]), hb + cn * CHUNK_ROWS * DIM, CHUNK_BYTES, f);
        }
    }

    partial[g][col] = acc;
    __syncthreads();

    if (tid < DIM4) {
        const float cnt = (float)(wcnt[0] + wcnt[1]);
        const float inv = 1.0f / fmaxf(cnt, 1.0f);

        float4 s0 = partial[0][tid];
        float4 s1 = partial[1][tid];
        float4 s2 = partial[2][tid];
        float4 s3 = partial[3][tid];
        float4 o4;
        o4.x = (s0.x + s1.x + s2.x + s3.x) * inv;
        o4.y = (s0.y + s1.y + s2.y + s3.y) * inv;
        o4.z = (s0.z + s1.z + s2.z + s3.z) * inv;
        o4.w = (s0.w + s1.w + s2.w + s3.w) * inv;

        __stcs(&reinterpret_cast<float4*>(out + (size_t)b * DIM)[tid], o4);
    }
}

extern "C" void kernel_launch(void* const* d_in, const int* in_sizes, int n_in,
                              void* d_out, int out_size)
{
    const float* h  = (const float*)d_in[0];
    const int*   op = (const int*)d_in[1];
    float*       o  = (float*)d_out;

    const int B = in_sizes[1] / NNODES;   // op_idx has B*N elements

    readout_kernel<<<B, 256>>>(h, op, o);
}

// round 11
// speedup vs baseline: 1.0007x; 1.0007x over previous
#include <cuda_runtime.h>
#include <cstdint>

// Masked per-graph mean pooling — FINAL (converged at the LTS path-independent
// throughput cap, ~6.3 TB/s; see B300_MICROARCH § L2: LDG.cv ≡ TMA).
// Inputs (metadata order):
//   d_in[0]: node_embeddings float32 [B*N, D] = [4096*64, 256]
//   d_in[1]: op_idx          int32   [B, N]   = [4096, 64]
// Output: float32 [B, D] = [4096, 256]
//
// out[b, :] = sum_{n: op[b,n]!=5} h[b,n,:] / max(count, 1)
//
// Shape: one CTA per graph, 256 threads.
//   g   = tid>>6 : row group (0..3), 16 rows each
//   col = tid&63 : float4 column
// Streaming loads (__ldcs, zero reuse) + streaming stores (__stcs).

#define SKIP_OP 5
#define NNODES  64
#define DIM     256
#define DIM4    (DIM / 4)   // 64 float4 per row

__global__ __launch_bounds__(256, 8)
void readout_kernel(const float* __restrict__ h,
                    const int* __restrict__ op,
                    float* __restrict__ out)
{
    const int b   = blockIdx.x;
    const int tid = threadIdx.x;

    __shared__ float  mask[NNODES];
    __shared__ float4 partial[4][DIM4];
    __shared__ int    wcnt[2];

    // Stage the per-node mask; count via warp ballot (warps 0 and 1 cover 64 nodes).
    if (tid < NNODES) {
        const bool keep = (op[(size_t)b * NNODES + tid] != SKIP_OP);
        mask[tid] = keep ? 1.0f : 0.0f;
        const unsigned bal = __ballot_sync(0xffffffffu, keep);
        if ((tid & 31) == 0) wcnt[tid >> 5] = __popc(bal);
    }
    __syncthreads();

    const int col = tid & (DIM4 - 1);   // float4 column 0..63
    const int g   = tid >> 6;           // row group 0..3

    const float4* hp = reinterpret_cast<const float4*>(
        h + (size_t)b * NNODES * DIM);

    float4 acc = make_float4(0.f, 0.f, 0.f, 0.f);

    // 16 strided iterations; block touches 4 contiguous rows (4 KB) per step.
#pragma unroll
    for (int r = g; r < NNODES; r += 4) {
        const float  m = mask[r];
        const float4 v = __ldcs(&hp[r * DIM4 + col]);   // evict-first stream
        acc.x = fmaf(m, v.x, acc.x);
        acc.y = fmaf(m, v.y, acc.y);
        acc.z = fmaf(m, v.z, acc.z);
        acc.w = fmaf(m, v.w, acc.w);
    }

    partial[g][col] = acc;
    __syncthreads();

    if (tid < DIM4) {
        const float cnt = (float)(wcnt[0] + wcnt[1]);
        const float inv = 1.0f / fmaxf(cnt, 1.0f);

        float4 s0 = partial[0][tid];
        float4 s1 = partial[1][tid];
        float4 s2 = partial[2][tid];
        float4 s3 = partial[3][tid];
        float4 s;
        s.x = (s0.x + s1.x + s2.x + s3.x) * inv;
        s.y = (s0.y + s1.y + s2.y + s3.y) * inv;
        s.z = (s0.z + s1.z + s2.z + s3.z) * inv;
        s.w = (s0.w + s1.w + s2.w + s3.w) * inv;

        __stcs(&reinterpret_cast<float4*>(out + (size_t)b * DIM)[tid], s);
    }
}

extern "C" void kernel_launch(void* const* d_in, const int* in_sizes, int n_in,
                              void* d_out, int out_size)
{
    const float* h  = (const float*)d_in[0];
    const int*   op = (const int*)d_in[1];
    float*       o  = (float*)d_out;

    const int B = in_sizes[1] / NNODES;   // op_idx has B*N elements

    readout_kernel<<<B, 256>>>(h, op, o);
}